// round 7
// baseline (speedup 1.0000x reference)
#include <cuda_runtime.h>
#include <cuda_bf16.h>
#include <cstdint>
#include <math.h>

// Problem constants
#define NB     64
#define NOBJ   5
#define CIN    3
#define HI     64
#define WI     96
#define HO     32
#define WO     48
#define NPOS   (HO*WO)          // 1536
#define COUT   128
#define PP     4
#define NT     (NB*NOBJ*NOBJ)   // 1600

#define NTHR   384              // 12 warps -> 3 per SMSP; 384 = 16x24 2x2-blocks
#define NWARP  (NTHR/32)

// Padded image buffer: [3][65][100] floats (stride 100 => 400B rows, 16B aligned)
#define IMG_STRIDE 100
#define IMG_BUF_ELEMS (3*65*IMG_STRIDE)      // 19500 floats = 78000 B
// Planes (bf16): [5 img][1536 pos][4] packed as (A0,A1),(B0,B1)
#define PL_BF16_ELEMS (5*NPOS*4)
#define SMEM_BYTES (2*IMG_BUF_ELEMS*4 + PL_BF16_ELEMS*2)   // 217440 B

__device__ float g_S[(size_t)NT * COUT];     // channel sums S[t][128]

typedef unsigned long long u64;

// ---- packed f32x2 helpers --------------------------------------------------
__device__ __forceinline__ u64 pack2(float lo, float hi) {
    u64 r; asm("mov.b64 %0, {%1, %2};" : "=l"(r) : "f"(lo), "f"(hi)); return r;
}
__device__ __forceinline__ float2 unpack2(u64 v) {
    float2 f; asm("mov.b64 {%0, %1}, %2;" : "=f"(f.x), "=f"(f.y) : "l"(v)); return f;
}
__device__ __forceinline__ u64 fma2(u64 a, u64 b, u64 c) {
    u64 d; asm("fma.rn.f32x2 %0, %1, %2, %3;" : "=l"(d) : "l"(a), "l"(b), "l"(c)); return d;
}
__device__ __forceinline__ u64 add2(u64 a, u64 b) {
    u64 d; asm("add.rn.f32x2 %0, %1, %2;" : "=l"(d) : "l"(a), "l"(b)); return d;
}

// ---- cp.async helpers -------------------------------------------------------
__device__ __forceinline__ void cp16(uint32_t dst, const void* src) {
    asm volatile("cp.async.cg.shared.global [%0], [%1], 16;\n" :: "r"(dst), "l"(src));
}
__device__ __forceinline__ void cp_commit() {
    asm volatile("cp.async.commit_group;\n");
}
template <int N> __device__ __forceinline__ void cp_wait() {
    asm volatile("cp.async.wait_group %0;\n" :: "n"(N));
}

// Async copy of one image (3x64x96 f32) into a padded smem buffer.
__device__ __forceinline__ void issue_image_copy(uint32_t buf_u32,
                                                 const float* __restrict__ img,
                                                 int tid) {
    for (int k = tid; k < 192*24; k += NTHR) {
        int row = k / 24, v = k % 24;         // row = c*64 + r
        int c = row >> 6, r = row & 63;
        const float* src = img + row*96 + v*4;
        uint32_t dst = buf_u32 + (uint32_t)(((c*65 + r)*IMG_STRIDE + v*4) * 4);
        cp16(dst, src);
    }
    cp_commit();
}

// ---------------------------------------------------------------------------
// Fused conv + pairwise-combine kernel, FFMA2 (f32x2) mainloop.
// CTA = (channel-pair g, batch b). Channels c0=2g, c1=2g+1.
// conv(concat(img_i,img_j), W) = conv(img_i, W_a) + conv(img_j, W_b).
// Each thread computes a 2x2 output block; filters packed pairwise into f32x2.
// ---------------------------------------------------------------------------
__global__ __launch_bounds__(NTHR, 1)
void fused_kernel(const float* __restrict__ input,   // [320][3][64][96]
                  const float* __restrict__ conv_w,  // [128][6][3][3]
                  const float* __restrict__ conv_b,  // [128]
                  float* __restrict__ S)             // [1600][128]
{
    extern __shared__ float sm[];
    float* buf[2] = { sm, sm + IMG_BUF_ELEMS };
    __nv_bfloat16* pl = (__nv_bfloat16*)(sm + 2*IMG_BUF_ELEMS);
    __shared__ float red[50][NWARP];

    const int g   = blockIdx.x;     // 0..63
    const int b   = blockIdx.y;     // 0..63
    const int tid = threadIdx.x;
    const int c0  = g*2, c1 = g*2 + 1;

    uint32_t buf_u32[2];
    buf_u32[0] = (uint32_t)__cvta_generic_to_shared(buf[0]);
    buf_u32[1] = (uint32_t)__cvta_generic_to_shared(buf[1]);

    // Packed filter pairs: wp01[t] = (W_a(c0)[t], W_b(c0)[t]), wp23 same for c1.
    u64 wp01[27], wp23[27];
    #pragma unroll
    for (int t = 0; t < 27; t++) {
        int ic = t / 9, kk = t % 9;
        wp01[t] = pack2(conv_w[(c0*6 + ic)*9 + kk], conv_w[(c0*6 + 3 + ic)*9 + kk]);
        wp23[t] = pack2(conv_w[(c1*6 + ic)*9 + kk], conv_w[(c1*6 + 3 + ic)*9 + kk]);
    }

    // Zero both buffers once (SAME zero-padding at row 64 / cols 96..99).
    for (int k = tid; k < 2*IMG_BUF_ELEMS; k += NTHR) sm[k] = 0.f;
    __syncthreads();

    const float* imgs = input + (size_t)b * NOBJ * (CIN*HI*WI);
    issue_image_copy(buf_u32[0], imgs + 0*(CIN*HI*WI), tid);
    issue_image_copy(buf_u32[1], imgs + 1*(CIN*HI*WI), tid);

    // 2x2 output block coords: 16 x 24 blocks = 384 threads.
    const int by = tid / 24, bx = tid % 24;
    const int iy = 4*by,     ix = 4*bx;
    const int pos_tl = (2*by)*WO + 2*bx;

    const float bias0 = conv_b[c0];
    const float bias1 = conv_b[c1];

    for (int i = 0; i < 5; i++) {
        if (i < 4) cp_wait<1>(); else cp_wait<0>();
        __syncthreads();

        const float* sb = buf[i & 1];

        // acc01[p] = (A0,B0) at pos p; acc23[p] = (A1,B1). p: tl,tr,bl,br
        u64 acc01[4], acc23[4];
        #pragma unroll
        for (int p = 0; p < 4; p++) { acc01[p] = 0ull; acc23[p] = 0ull; }

        #pragma unroll
        for (int c = 0; c < 3; c++) {
            #pragma unroll
            for (int r = 0; r < 5; r++) {
                const float* rp = sb + (c*65 + iy + r)*IMG_STRIDE + ix;
                float4 v4 = *(const float4*)rp;      // 16B-aligned
                float v[5] = { v4.x, v4.y, v4.z, v4.w, rp[4] };
                u64 vv[5];
                #pragma unroll
                for (int k = 0; k < 5; k++) vv[k] = pack2(v[k], v[k]);

                if (r < 3) {                          // top pos pair, ky = r
                    #pragma unroll
                    for (int kx = 0; kx < 3; kx++) {
                        int t = c*9 + r*3 + kx;
                        acc01[0] = fma2(wp01[t], vv[kx],   acc01[0]);
                        acc01[1] = fma2(wp01[t], vv[kx+2], acc01[1]);
                        acc23[0] = fma2(wp23[t], vv[kx],   acc23[0]);
                        acc23[1] = fma2(wp23[t], vv[kx+2], acc23[1]);
                    }
                }
                if (r >= 2) {                         // bottom pos pair, ky = r-2
                    #pragma unroll
                    for (int kx = 0; kx < 3; kx++) {
                        int t = c*9 + (r-2)*3 + kx;
                        acc01[2] = fma2(wp01[t], vv[kx],   acc01[2]);
                        acc01[3] = fma2(wp01[t], vv[kx+2], acc01[3]);
                        acc23[2] = fma2(wp23[t], vv[kx],   acc23[2]);
                        acc23[3] = fma2(wp23[t], vv[kx+2], acc23[3]);
                    }
                }
            }
        }

        // Store packed planes as (A0,A1),(B0,B1); bias folded into A halves.
        const int poss[4] = { pos_tl, pos_tl + 1, pos_tl + WO, pos_tl + WO + 1 };
        #pragma unroll
        for (int p = 0; p < 4; p++) {
            float2 f01 = unpack2(acc01[p]);   // (a0, b0)
            float2 f23 = unpack2(acc23[p]);   // (a1, b1)
            union { __nv_bfloat162 h2[2]; uint2 u; } cv;
            cv.h2[0] = __floats2bfloat162_rn(f01.x + bias0, f23.x + bias1); // (A0,A1)
            cv.h2[1] = __floats2bfloat162_rn(f01.y,         f23.y);         // (B0,B1)
            *(uint2*)(pl + ((size_t)i*NPOS + poss[p])*4) = cv.u;
        }

        __syncthreads();
        if (i < 3)
            issue_image_copy(buf_u32[i & 1], imgs + (i+2)*(CIN*HI*WI), tid);
    }
    __syncthreads();

    // Combine (packed over channels): accp[q] accumulates (t + |t|) where
    // t = (A0_i+B0_j, A1_i+B1_j); relu(x) = (x+|x|)/2 exactly, 1/2 at store.
    u64 accp[25];
    #pragma unroll
    for (int q = 0; q < 25; q++) accp[q] = 0ull;
    const u64 ABSM = 0x7FFFFFFF7FFFFFFFull;

    #pragma unroll
    for (int pp = 0; pp < 4; pp++) {
        int pos = tid + pp*NTHR;
        u64 uA[5], uB[5];
        #pragma unroll
        for (int i = 0; i < 5; i++) {
            uint2 u = *(const uint2*)(pl + ((size_t)i*NPOS + pos)*4);
            float2 fa = __bfloat1622float2(*(__nv_bfloat162*)&u.x);  // (A0,A1)
            float2 fb = __bfloat1622float2(*(__nv_bfloat162*)&u.y);  // (B0,B1)
            uA[i] = pack2(fa.x, fa.y);
            uB[i] = pack2(fb.x, fb.y);
        }
        #pragma unroll
        for (int i = 0; i < 5; i++)
            #pragma unroll
            for (int j = 0; j < 5; j++) {
                u64 t = add2(uA[i], uB[j]);
                u64 a = t & ABSM;
                int q = i*5 + j;
                accp[q] = add2(accp[q], t);
                accp[q] = add2(accp[q], a);
            }
    }

    // Shuffle-first reduction.
    const int lane = tid & 31, wid = tid >> 5;
    #pragma unroll
    for (int q = 0; q < 25; q++) {
        float2 f = unpack2(accp[q]);
        float s0 = f.x, s1 = f.y;
        #pragma unroll
        for (int off = 16; off; off >>= 1) {
            s0 += __shfl_xor_sync(0xFFFFFFFFu, s0, off);
            s1 += __shfl_xor_sync(0xFFFFFFFFu, s1, off);
        }
        if (lane == 0) {
            red[q*2 + 0][wid] = s0;
            red[q*2 + 1][wid] = s1;
        }
    }
    __syncthreads();

    if (tid < 50) {
        float s = 0.f;
        #pragma unroll
        for (int k = 0; k < NWARP; k++) s += red[tid][k];
        int q  = tid >> 1;
        int ch = (tid & 1) ? c1 : c0;
        S[(size_t)(b*25 + q)*COUT + ch] = 0.5f * s;   // undo the 2x from t+|t|
    }
}

// ---------------------------------------------------------------------------
// logits: warp per tuple, coalesced S reads, shuffle reduce.
// ---------------------------------------------------------------------------
__global__ __launch_bounds__(256)
void logits_kernel(const float* __restrict__ S,
                   const float* __restrict__ w2,    // [4][32]
                   const float* __restrict__ b2,    // [4]
                   const float* __restrict__ temp,
                   float* __restrict__ out)         // [1600][4]
{
    const int lane = threadIdx.x & 31;
    const int t = blockIdx.x * 8 + (threadIdx.x >> 5);
    if (t >= NT) return;

    float s[4];
    #pragma unroll
    for (int p = 0; p < 4; p++)
        s[p] = S[(size_t)t*COUT + p*32 + lane] * w2[p*32 + lane];
    #pragma unroll
    for (int off = 16; off; off >>= 1)
        #pragma unroll
        for (int p = 0; p < 4; p++)
            s[p] += __shfl_xor_sync(0xFFFFFFFFu, s[p], off);

    if (lane < 4) {
        float invT = 1.0f / (*temp);
        float logit = s[lane] * (1.0f / (float)NPOS) + b2[lane];
        out[t*4 + lane] = 1.0f / (1.0f + expf(-logit * invT));
    }
}

// adj[b][t] = (t / 25 == b)
__global__ void adj_kernel(float* __restrict__ out)
{
    int idx = blockIdx.x * blockDim.x + threadIdx.x;
    if (idx >= NB * NT) return;
    int b = idx / NT;
    int t = idx % NT;
    out[idx] = (t / (NOBJ*NOBJ) == b) ? 1.0f : 0.0f;
}

// ---------------------------------------------------------------------------
extern "C" void kernel_launch(void* const* d_in, const int* in_sizes, int n_in,
                              void* d_out, int out_size)
{
    const float* state      = (const float*)d_in[0];
    const float* state_next = (const float*)d_in[1];
    const float* conv_w     = (const float*)d_in[2];
    const float* conv_b     = (const float*)d_in[3];
    const float* w2         = (const float*)d_in[4];
    const float* b2         = (const float*)d_in[5];
    // d_in[6] = n_obj (constant NOBJ), d_in[7] = temp
    const float* temp       = (const float*)d_in[7];
    float* out = (float*)d_out;

    float* S;
    cudaGetSymbolAddress((void**)&S, g_S);

    cudaFuncSetAttribute(fused_kernel, cudaFuncAttributeMaxDynamicSharedMemorySize,
                         SMEM_BYTES);

    dim3 grid(64 /*chan pair*/, 64 /*batch*/);

    fused_kernel<<<grid, NTHR, SMEM_BYTES>>>(state, conv_w, conv_b, S);
    logits_kernel<<<200, 256>>>(S, w2, b2, temp, out);                 // preds

    fused_kernel<<<grid, NTHR, SMEM_BYTES>>>(state_next, conv_w, conv_b, S);
    logits_kernel<<<200, 256>>>(S, w2, b2, temp, out + NT*PP);         // preds_next

    adj_kernel<<<(NB*NT + 255)/256, 256>>>(out + 2*NT*PP);             // adj
}

// round 8
// speedup vs baseline: 1.2641x; 1.2641x over previous
#include <cuda_runtime.h>
#include <cuda_bf16.h>
#include <cstdint>
#include <math.h>

// Problem constants
#define NB     64
#define NOBJ   5
#define CIN    3
#define HI     64
#define WI     96
#define HO     32
#define WO     48
#define NPOS   (HO*WO)          // 1536
#define COUT   128
#define PP     4
#define NT     (NB*NOBJ*NOBJ)   // 1600

#define NTHR   384              // 12 warps -> 3 per SMSP; 384 = 16x24 2x2-blocks
#define NWARP  (NTHR/32)

// Unpadded image buffer: [3][64][96] floats = 18432 floats = 73728 B (TMA bulk)
#define IMG_ELEMS (CIN*HI*WI)                  // 18432
#define IMG_BYTES (IMG_ELEMS*4)                // 73728
// Planes (bf16): [5 img][1536 pos][4] packed (A0,B0,A1,B1)
#define PL_BF16_ELEMS (5*NPOS*4)
#define SMEM_BYTES (2*IMG_BYTES + PL_BF16_ELEMS*2)   // 147456 + 61440 = 208896 B

__device__ float g_S[(size_t)NT * COUT];     // channel sums S[t][128]

// ---- TMA bulk + mbarrier helpers -------------------------------------------
__device__ __forceinline__ void mbar_init(uint32_t addr, uint32_t count) {
    asm volatile("mbarrier.init.shared.b64 [%0], %1;" :: "r"(addr), "r"(count) : "memory");
}
__device__ __forceinline__ void mbar_expect_tx(uint32_t addr, uint32_t bytes) {
    asm volatile("mbarrier.arrive.expect_tx.shared.b64 _, [%0], %1;"
                 :: "r"(addr), "r"(bytes) : "memory");
}
__device__ __forceinline__ void tma_bulk_g2s(uint32_t dst, const void* src,
                                             uint32_t bytes, uint32_t mbar) {
    asm volatile("cp.async.bulk.shared::cta.global.mbarrier::complete_tx::bytes "
                 "[%0], [%1], %2, [%3];"
                 :: "r"(dst), "l"(src), "r"(bytes), "r"(mbar) : "memory");
}
__device__ __forceinline__ void mbar_wait(uint32_t mbar, uint32_t parity) {
    uint32_t done;
    asm volatile(
        "{\n\t.reg .pred p;\n\t"
        "mbarrier.try_wait.parity.acquire.cta.shared::cta.b64 p, [%1], %2;\n\t"
        "selp.b32 %0, 1, 0, p;\n\t}"
        : "=r"(done) : "r"(mbar), "r"(parity) : "memory");
    if (!done) {
        asm volatile(
            "{\n\t.reg .pred P1;\n\t"
            "WAIT_LOOP_%=:\n\t"
            "mbarrier.try_wait.parity.acquire.cta.shared::cta.b64 P1, [%0], %1, 0x989680;\n\t"
            "@P1 bra.uni WAIT_DONE_%=;\n\t"
            "bra.uni WAIT_LOOP_%=;\n\t"
            "WAIT_DONE_%=:\n\t}"
            :: "r"(mbar), "r"(parity) : "memory");
    }
}

// ---------------------------------------------------------------------------
// Fused conv + pairwise-combine kernel.
// CTA = (channel-pair g, batch b). Channels c0=2g, c1=2g+1.
// conv(concat(img_i,img_j), W) = conv(img_i, W_a) + conv(img_j, W_b).
// Images arrive via single-instruction TMA bulk copies (double buffered);
// SAME padding handled by predicates (row 64 / col 96 only).
// ---------------------------------------------------------------------------
__global__ __launch_bounds__(NTHR, 1)
void fused_kernel(const float* __restrict__ input,   // [320][3][64][96]
                  const float* __restrict__ conv_w,  // [128][6][3][3]
                  const float* __restrict__ conv_b,  // [128]
                  float* __restrict__ S)             // [1600][128]
{
    extern __shared__ float sm[];
    float* buf[2] = { sm, sm + IMG_ELEMS };
    __nv_bfloat16* pl = (__nv_bfloat16*)(sm + 2*IMG_ELEMS);
    __shared__ float red[50][NWARP];
    __shared__ __align__(8) unsigned long long mbar_store[2];

    const int g   = blockIdx.x;     // 0..63
    const int b   = blockIdx.y;     // 0..63
    const int tid = threadIdx.x;
    const int c0  = g*2, c1 = g*2 + 1;

    uint32_t buf_u32[2];
    buf_u32[0] = (uint32_t)__cvta_generic_to_shared(buf[0]);
    buf_u32[1] = (uint32_t)__cvta_generic_to_shared(buf[1]);
    uint32_t mbar_u32 = (uint32_t)__cvta_generic_to_shared(mbar_store);

    // Filter halves in registers (uniform loads -> broadcast)
    float w[4][27];
    #pragma unroll
    for (int t = 0; t < 27; t++) {
        int ic = t / 9, kk = t % 9;
        w[0][t] = conv_w[(c0*6 +     ic)*9 + kk];
        w[1][t] = conv_w[(c0*6 + 3 + ic)*9 + kk];
        w[2][t] = conv_w[(c1*6 +     ic)*9 + kk];
        w[3][t] = conv_w[(c1*6 + 3 + ic)*9 + kk];
    }
    const float bias0 = conv_b[c0];
    const float bias1 = conv_b[c1];

    const float* imgs = input + (size_t)b * NOBJ * IMG_ELEMS;

    // mbarrier init + prime the TMA pipeline (images 0 and 1).
    if (tid == 0) {
        mbar_init(mbar_u32 + 0, 1);
        mbar_init(mbar_u32 + 8, 1);
    }
    __syncthreads();
    if (tid == 0) {
        mbar_expect_tx(mbar_u32 + 0, IMG_BYTES);
        tma_bulk_g2s(buf_u32[0], imgs + 0*IMG_ELEMS, IMG_BYTES, mbar_u32 + 0);
        mbar_expect_tx(mbar_u32 + 8, IMG_BYTES);
        tma_bulk_g2s(buf_u32[1], imgs + 1*IMG_ELEMS, IMG_BYTES, mbar_u32 + 8);
    }

    // 2x2 output block coords: 16 x 24 blocks = 384 threads.
    const int by = tid / 24, bx = tid % 24;
    const int iy = 4*by,     ix = 4*bx;
    const int pos_tl = (2*by)*WO + 2*bx;
    const bool right_edge = (bx == 23);      // col ix+4 == 96 -> SAME pad

    for (int i = 0; i < 5; i++) {
        mbar_wait(mbar_u32 + 8*(i & 1), (i >> 1) & 1);   // image i ready

        const float* sb = buf[i & 1];

        // acc[f][p]: f = filter half (A0,B0,A1,B1), p = pos (tl,tr,bl,br)
        float acc[4][4];
        #pragma unroll
        for (int f = 0; f < 4; f++)
            #pragma unroll
            for (int p = 0; p < 4; p++) acc[f][p] = 0.f;

        #pragma unroll
        for (int c = 0; c < 3; c++) {
            #pragma unroll
            for (int r = 0; r < 5; r++) {
                float v[5];
                if (iy + r >= HI) {                   // row 64 == SAME pad row
                    #pragma unroll
                    for (int k = 0; k < 5; k++) v[k] = 0.f;
                } else {
                    const float* rp = sb + (c*HI + iy + r)*WI + ix;
                    float4 v4 = *(const float4*)rp;   // 16B-aligned (384B rows)
                    v[0] = v4.x; v[1] = v4.y; v[2] = v4.z; v[3] = v4.w;
                    v[4] = right_edge ? 0.f : rp[4];
                }

                if (r < 3) {                          // top row pair, ky = r
                    #pragma unroll
                    for (int kx = 0; kx < 3; kx++) {
                        int t = c*9 + r*3 + kx;
                        #pragma unroll
                        for (int f = 0; f < 4; f++) {
                            acc[f][0] = fmaf(w[f][t], v[kx],   acc[f][0]); // tl
                            acc[f][1] = fmaf(w[f][t], v[kx+2], acc[f][1]); // tr
                        }
                    }
                }
                if (r >= 2) {                         // bottom row pair, ky = r-2
                    #pragma unroll
                    for (int kx = 0; kx < 3; kx++) {
                        int t = c*9 + (r-2)*3 + kx;
                        #pragma unroll
                        for (int f = 0; f < 4; f++) {
                            acc[f][2] = fmaf(w[f][t], v[kx],   acc[f][2]); // bl
                            acc[f][3] = fmaf(w[f][t], v[kx+2], acc[f][3]); // br
                        }
                    }
                }
            }
        }

        // Store 4 positions, packed bf16x4 (A0,B0,A1,B1); bias folded into A.
        const int poss[4] = { pos_tl, pos_tl + 1, pos_tl + WO, pos_tl + WO + 1 };
        #pragma unroll
        for (int p = 0; p < 4; p++) {
            union { __nv_bfloat162 h2[2]; uint2 u; } cv;
            cv.h2[0] = __floats2bfloat162_rn(acc[0][p] + bias0, acc[1][p]);
            cv.h2[1] = __floats2bfloat162_rn(acc[2][p] + bias1, acc[3][p]);
            *(uint2*)(pl + ((size_t)i*NPOS + poss[p])*4) = cv.u;
        }

        __syncthreads();                     // all threads done reading buf[i&1]
        if (i < 3 && tid == 0) {             // refill with image i+2
            uint32_t m = mbar_u32 + 8*(i & 1);
            mbar_expect_tx(m, IMG_BYTES);
            tma_bulk_g2s(buf_u32[i & 1], imgs + (i+2)*IMG_ELEMS, IMG_BYTES, m);
        }
    }
    __syncthreads();                         // all planes visible

    // Combine: 25 pairs x 2 channels, per-thread accumulation over 4 positions
    float acc0[25], acc1[25];
    #pragma unroll
    for (int q = 0; q < 25; q++) { acc0[q] = 0.f; acc1[q] = 0.f; }

    #pragma unroll
    for (int pp = 0; pp < 4; pp++) {
        int pos = tid + pp*NTHR;
        float A0[5], B0[5], A1[5], B1[5];
        #pragma unroll
        for (int i = 0; i < 5; i++) {
            uint2 u = *(const uint2*)(pl + ((size_t)i*NPOS + pos)*4);
            float2 f01 = __bfloat1622float2(*(__nv_bfloat162*)&u.x);
            float2 f23 = __bfloat1622float2(*(__nv_bfloat162*)&u.y);
            A0[i] = f01.x; B0[i] = f01.y;
            A1[i] = f23.x; B1[i] = f23.y;
        }
        #pragma unroll
        for (int i = 0; i < 5; i++)
            #pragma unroll
            for (int j = 0; j < 5; j++) {
                acc0[i*5 + j] += fmaxf(A0[i] + B0[j], 0.f);
                acc1[i*5 + j] += fmaxf(A1[i] + B1[j], 0.f);
            }
    }

    // Shuffle-first reduction: warp-reduce each of the 50 accumulators.
    const int lane = tid & 31, wid = tid >> 5;
    #pragma unroll
    for (int q = 0; q < 25; q++) {
        float s0 = acc0[q], s1 = acc1[q];
        #pragma unroll
        for (int off = 16; off; off >>= 1) {
            s0 += __shfl_xor_sync(0xFFFFFFFFu, s0, off);
            s1 += __shfl_xor_sync(0xFFFFFFFFu, s1, off);
        }
        if (lane == 0) {
            red[q*2 + 0][wid] = s0;
            red[q*2 + 1][wid] = s1;
        }
    }
    __syncthreads();

    if (tid < 50) {
        float s = 0.f;
        #pragma unroll
        for (int k = 0; k < NWARP; k++) s += red[tid][k];
        int q  = tid >> 1;
        int ch = (tid & 1) ? c1 : c0;
        S[(size_t)(b*25 + q)*COUT + ch] = s;
    }
}

// ---------------------------------------------------------------------------
// logits: warp per tuple, coalesced S reads, shuffle reduce.
// ---------------------------------------------------------------------------
__global__ __launch_bounds__(256)
void logits_kernel(const float* __restrict__ S,
                   const float* __restrict__ w2,    // [4][32]
                   const float* __restrict__ b2,    // [4]
                   const float* __restrict__ temp,
                   float* __restrict__ out)         // [1600][4]
{
    const int lane = threadIdx.x & 31;
    const int t = blockIdx.x * 8 + (threadIdx.x >> 5);
    if (t >= NT) return;

    float s[4];
    #pragma unroll
    for (int p = 0; p < 4; p++)
        s[p] = S[(size_t)t*COUT + p*32 + lane] * w2[p*32 + lane];
    #pragma unroll
    for (int off = 16; off; off >>= 1)
        #pragma unroll
        for (int p = 0; p < 4; p++)
            s[p] += __shfl_xor_sync(0xFFFFFFFFu, s[p], off);

    if (lane < 4) {
        float invT = 1.0f / (*temp);
        float logit = s[lane] * (1.0f / (float)NPOS) + b2[lane];
        out[t*4 + lane] = 1.0f / (1.0f + expf(-logit * invT));
    }
}

// adj[b][t] = (t / 25 == b)
__global__ void adj_kernel(float* __restrict__ out)
{
    int idx = blockIdx.x * blockDim.x + threadIdx.x;
    if (idx >= NB * NT) return;
    int b = idx / NT;
    int t = idx % NT;
    out[idx] = (t / (NOBJ*NOBJ) == b) ? 1.0f : 0.0f;
}

// ---------------------------------------------------------------------------
extern "C" void kernel_launch(void* const* d_in, const int* in_sizes, int n_in,
                              void* d_out, int out_size)
{
    const float* state      = (const float*)d_in[0];
    const float* state_next = (const float*)d_in[1];
    const float* conv_w     = (const float*)d_in[2];
    const float* conv_b     = (const float*)d_in[3];
    const float* w2         = (const float*)d_in[4];
    const float* b2         = (const float*)d_in[5];
    // d_in[6] = n_obj (constant NOBJ), d_in[7] = temp
    const float* temp       = (const float*)d_in[7];
    float* out = (float*)d_out;

    float* S;
    cudaGetSymbolAddress((void**)&S, g_S);

    cudaFuncSetAttribute(fused_kernel, cudaFuncAttributeMaxDynamicSharedMemorySize,
                         SMEM_BYTES);

    dim3 grid(64 /*chan pair*/, 64 /*batch*/);

    fused_kernel<<<grid, NTHR, SMEM_BYTES>>>(state, conv_w, conv_b, S);
    logits_kernel<<<200, 256>>>(S, w2, b2, temp, out);                 // preds

    fused_kernel<<<grid, NTHR, SMEM_BYTES>>>(state_next, conv_w, conv_b, S);
    logits_kernel<<<200, 256>>>(S, w2, b2, temp, out + NT*PP);         // preds_next

    adj_kernel<<<(NB*NT + 255)/256, 256>>>(out + 2*NT*PP);             // adj
}